// round 16
// baseline (speedup 1.0000x reference)
#include <cuda_runtime.h>
#include <cuda.h>
#include <cstdint>
#include <cstddef>

// ---------------------------------------------------------------------------
// Problem constants
// ---------------------------------------------------------------------------
#define B_DIM 16
#define S_DIM 2048
#define D_DIM 128
#define NT 32             // 64-row k-tiles

// exp(x) = exp2(x*log2e); fold log2e/sqrt(128) into Q pre-scale
#define CQ_SCALE ((float)(1.4426950408889634 / 11.313708498984761))

// SMEM (per CTA, 113KB => 2 CTAs/SM):
// [0,256) rowsum f32[64]; [512..536) mbarriers;
// Q 32K @1024 | K 32K | V 32K | P 16K   (K,V single-buffered)
#define QBUF_OFF 1024
#define KBUF_OFF (QBUF_OFF + 32768)
#define VBUF_OFF (KBUF_OFF + 32768)
#define PBUF_OFF (VBUF_OFF + 32768)
#define SMEM_BYTES (PBUF_OFF + 16384)   // 115712 B = 113 KB

// ---------------------------------------------------------------------------
// Device scratch (static; no allocations allowed)
// ---------------------------------------------------------------------------
__device__ float g_Qr[B_DIM * S_DIM * D_DIM];                 // Q*(log2e/sqrt d), tf32-rounded
__device__ float g_Kr[B_DIM * S_DIM * D_DIM];                 // K tf32-rounded
__device__ float g_VT[B_DIM * D_DIM * S_DIM];                 // V^T [b][d][s], tf32-rounded
__device__ unsigned long long g_Mb[B_DIM * S_DIM * (S_DIM / 64)];  // mask bitpack

// ---------------------------------------------------------------------------
// PTX helpers
// ---------------------------------------------------------------------------
__device__ __forceinline__ uint32_t smem_u32(const void* p) {
    uint32_t a;
    asm("{ .reg .u64 t; cvta.to.shared.u64 t, %1; cvt.u32.u64 %0, t; }" : "=r"(a) : "l"(p));
    return a;
}
// cvt.rna.tf32.f32 requires a .b32 destination register.
__device__ __forceinline__ float rna_tf32(float x) {
    uint32_t r; asm("cvt.rna.tf32.f32 %0, %1;" : "=r"(r) : "f"(x));
    return __uint_as_float(r);
}
__device__ __forceinline__ float ex2f(float x) {
    float r; asm("ex2.approx.f32 %0, %1;" : "=f"(r) : "f"(x)); return r;
}

#define MBAR_INIT(a, c) \
    asm volatile("mbarrier.init.shared.b64 [%0], %1;" :: "r"(a), "r"((uint32_t)(c)) : "memory")
#define MBAR_EXPECT_TX(a, n) \
    asm volatile("mbarrier.arrive.expect_tx.shared.b64 _, [%0], %1;" :: "r"(a), "r"((uint32_t)(n)) : "memory")

#define MBAR_WAIT(a, ph) do {                                                     \
    uint32_t _m = (a), _p = (uint32_t)(ph), _d;                                   \
    asm volatile("{\n\t.reg .pred p;\n\t"                                         \
        "mbarrier.try_wait.parity.acquire.cta.shared::cta.b64 p, [%1], %2;\n\t"   \
        "selp.b32 %0, 1, 0, p;\n\t}"                                              \
        : "=r"(_d) : "r"(_m), "r"(_p) : "memory");                                \
    if (!_d) {                                                                    \
        asm volatile("{\n\t.reg .pred P1;\n\t"                                    \
            "WL_%=:\n\t"                                                          \
            "mbarrier.try_wait.parity.acquire.cta.shared::cta.b64 P1, [%0], %1, 0x989680;\n\t" \
            "@P1 bra.uni WD_%=;\n\t"                                              \
            "bra.uni WL_%=;\n\t"                                                  \
            "WD_%=:\n\t}"                                                         \
            :: "r"(_m), "r"(_p) : "memory");                                      \
    }                                                                             \
} while (0)

// Quad named barrier: 128 threads (warps mchunk, mchunk+4, mchunk+8, mchunk+12)
#define QUAD_BAR(id) \
    asm volatile("bar.sync %0, 128;" :: "r"((uint32_t)(id)) : "memory")

#define TMA3D(dst, map, x, y, z, mb)                                              \
    asm volatile("cp.async.bulk.tensor.3d.shared::cta.global.tile.mbarrier::complete_tx::bytes " \
                 "[%0], [%1, {%2, %3, %4}], [%5];"                                \
                 :: "r"(dst), "l"(map), "r"((int)(x)), "r"((int)(y)), "r"((int)(z)), "r"(mb) : "memory")

// Swizzled address of f32 element (row, col): region = 32 f32-cols wide,
// rows*128B tall; rshift = log2(region bytes). TMA SW128 swizzle inside.
__device__ __forceinline__ uint32_t swa2(uint32_t buf, int row, int col, int rshift) {
    uint32_t byte = (uint32_t)(row * 128 + (col & 31) * 4);
    return buf + (((uint32_t)col >> 5) << rshift) + (byte ^ ((byte >> 3) & 0x70));
}

__device__ __forceinline__ void ldsm4(uint32_t addr, uint32_t* r) {
    asm volatile("ldmatrix.sync.aligned.m8n8.x4.shared.b16 {%0,%1,%2,%3}, [%4];"
                 : "=r"(r[0]), "=r"(r[1]), "=r"(r[2]), "=r"(r[3]) : "r"(addr));
}

// Non-volatile: pure register op; lets the compiler schedule MMAs freely.
__device__ __forceinline__ void mma8(float* c, const uint32_t* a, uint32_t b0, uint32_t b1) {
    asm("mma.sync.aligned.m16n8k8.row.col.f32.tf32.tf32.f32 "
        "{%0,%1,%2,%3}, {%4,%5,%6,%7}, {%8,%9}, {%0,%1,%2,%3};"
        : "+f"(c[0]), "+f"(c[1]), "+f"(c[2]), "+f"(c[3])
        : "r"(a[0]), "r"(a[1]), "r"(a[2]), "r"(a[3]), "r"(b0), "r"(b1));
}

__device__ __forceinline__ void sts2(uint32_t addr, float x, float y) {
    asm volatile("st.shared.v2.f32 [%0], {%1,%2};" :: "r"(addr), "f"(x), "f"(y) : "memory");
}

// ---------------------------------------------------------------------------
// Prep kernels (unchanged)
// ---------------------------------------------------------------------------
__global__ void prep_qk(const float4* __restrict__ q, const float4* __restrict__ k,
                        float4* __restrict__ qo, float4* __restrict__ ko) {
    int i = blockIdx.x * blockDim.x + threadIdx.x;
    float4 a = q[i];
    a.x = rna_tf32(a.x * CQ_SCALE); a.y = rna_tf32(a.y * CQ_SCALE);
    a.z = rna_tf32(a.z * CQ_SCALE); a.w = rna_tf32(a.w * CQ_SCALE);
    qo[i] = a;
    float4 b = k[i];
    b.x = rna_tf32(b.x); b.y = rna_tf32(b.y);
    b.z = rna_tf32(b.z); b.w = rna_tf32(b.w);
    ko[i] = b;
}

__global__ void prep_vt(const float* __restrict__ v, float* __restrict__ vt) {
    __shared__ float t[32][33];
    int b = blockIdx.z;
    int s0 = blockIdx.x * 32, d0 = blockIdx.y * 32;
    const float* vb = v + (size_t)b * S_DIM * D_DIM;
    float* vtb = vt + (size_t)b * D_DIM * S_DIM;
    t[threadIdx.y][threadIdx.x] =
        rna_tf32(vb[(size_t)(s0 + threadIdx.y) * D_DIM + d0 + threadIdx.x]);
    __syncthreads();
    vtb[(size_t)(d0 + threadIdx.y) * S_DIM + s0 + threadIdx.x] = t[threadIdx.x][threadIdx.y];
}

// Mask arrives as 4-byte elements (verified in R7 profile: 264MB DRAM read).
// out byte i <- mask elements [8i, 8i+8); bit j of byte i = element 8i+j.
__global__ void prep_mask(const uint4* __restrict__ m, unsigned char* __restrict__ o) {
    int i = blockIdx.x * blockDim.x + threadIdx.x;
    const uint4* p = m + (size_t)i * 2;
    uint4 a = p[0], b = p[1];
    unsigned v =
        (a.x != 0u ? 1u : 0u) | (a.y != 0u ? 2u : 0u) |
        (a.z != 0u ? 4u : 0u) | (a.w != 0u ? 8u : 0u) |
        (b.x != 0u ? 16u : 0u) | (b.y != 0u ? 32u : 0u) |
        (b.z != 0u ? 64u : 0u) | (b.w != 0u ? 128u : 0u);
    o[i] = (unsigned char)v;
}

// ---------------------------------------------------------------------------
// Main fused attention kernel — 64 q-rows/CTA, 512 threads (16 warps),
// 2 CTAs/SM (32 warps/SM), 64-row k-tiles, single-buffered K/V,
// software-pipelined inner loops (from R15).
// Warp role: mchunk = wid&3 (16 q-rows), quad = wid>>2 (0..3).
// S-phase: warp = 16m x 16n (n cols [16*quad,+16)).
// O-phase: warp = 16m x 32d (d cols [32*quad,+32)); A = P(16m x 64k) spans
// all 4 quads of the mchunk -> QUAD_BAR for P visibility.
// ---------------------------------------------------------------------------
__global__ void __launch_bounds__(512, 2) attn_main(
    const __grid_constant__ CUtensorMap qmap,   // box {32,64}
    const __grid_constant__ CUtensorMap kmap,   // box {32,64}
    const __grid_constant__ CUtensorMap vmap,   // box {32,128}
    const unsigned long long* __restrict__ mbits,
    float* __restrict__ out)
{
    extern __shared__ char smem[];
    float* rs = (float*)smem;               // rowsum[64]
    const uint32_t sb = smem_u32(smem);
    const uint32_t kbar = sb + 512, vbar = sb + 520;
    const uint32_t QBUF = sb + QBUF_OFF, KBUF = sb + KBUF_OFF;
    const uint32_t VBUF = sb + VBUF_OFF, PBUF = sb + PBUF_OFF;

    const int tid = threadIdx.x, wid = tid >> 5, lane = tid & 31;
    const int mchunk = wid & 3, quad = wid >> 2;
    const int tig = lane & 3, g = lane >> 2;
    const int b = blockIdx.x >> 5, qt = blockIdx.x & 31;

    // ldmatrix lane-role rows
    const int arow0  = 16 * mchunk + (lane & 7) + ((lane >> 3) & 1) * 8;  // A rows (m16)
    const int brow_s = 16 * quad + (lane & 7) + ((lane >> 4) & 1) * 8;    // S-phase B (n16)
    const int brow_o = 32 * quad + (lane & 7) + ((lane >> 4) & 1) * 8;    // O-phase B (+16*nbp, nbp<2)
    const int acsel = ((lane >> 4) & 1) * 4;
    const int bcsel = ((lane >> 3) & 1) * 4;

    if (tid < 64) rs[tid] = 0.0f;
    if (tid == 0) { MBAR_INIT(kbar, 1); MBAR_INIT(vbar, 1); }
    __syncthreads();

    // Prologue: Q (32K) + K(0) (32K) on kbar; V(0) (32K) on vbar
    if (tid == 0) {
        MBAR_EXPECT_TX(kbar, 65536);
#pragma unroll
        for (int c = 0; c < 4; c++) {
            TMA3D(QBUF + c * 8192, &qmap, 32 * c, qt * 64, b, kbar);
            TMA3D(KBUF + c * 8192, &kmap, 32 * c, 0, b, kbar);
        }
        MBAR_EXPECT_TX(vbar, 32768);
#pragma unroll
        for (int c = 0; c < 2; c++)
            TMA3D(VBUF + c * 16384, &vmap, 32 * c, 0, b, vbar);
    }

    float oacc[4][4];
#pragma unroll
    for (int nb = 0; nb < 4; nb++)
#pragma unroll
        for (int i = 0; i < 4; i++) oacc[nb][i] = 0.0f;

    float rsum[2] = {0.f, 0.f};
    const size_t mrow_base = ((size_t)b * S_DIM + qt * 64) * (S_DIM / 64);
    const int r0m = 16 * mchunk + g;

    for (int j = 0; j < NT; j++) {
        const int ph = j & 1;

        // Top-of-tile rendezvous (j>0): all warps done O(j-1) -> V buffer free.
        if (j > 0) {
            __syncthreads();
            if (tid == 0) {
                MBAR_EXPECT_TX(vbar, 32768);
#pragma unroll
                for (int c = 0; c < 2; c++)
                    TMA3D(VBUF + c * 16384, &vmap, j * 64 + 32 * c, 0, b, vbar);
            }
        }

        // Mask u64s (issued before barrier wait to hide latency)
        unsigned long long mrow0 = __ldg(mbits + mrow_base + (size_t)r0m * 32 + j);
        unsigned long long mrow1 = __ldg(mbits + mrow_base + (size_t)(r0m + 8) * 32 + j);

        MBAR_WAIT(kbar, ph);

        // ---- S-phase: S(16m x 16n per warp) over d (16 k8-steps), pipelined ----
        float sacc[2][4];
#pragma unroll
        for (int nb = 0; nb < 2; nb++)
#pragma unroll
            for (int i = 0; i < 4; i++) sacc[nb][i] = 0.0f;

        {
            uint32_t af[2][4], bf[2][4];
            ldsm4(swa2(QBUF, arow0, acsel, 13), af[0]);
            ldsm4(swa2(KBUF, brow_s, bcsel, 13), bf[0]);
#pragma unroll
            for (int kk = 0; kk < 16; kk++) {
                const int cur = kk & 1, nxt = cur ^ 1;
                if (kk < 15) {
                    ldsm4(swa2(QBUF, arow0, 8 * (kk + 1) + acsel, 13), af[nxt]);
                    ldsm4(swa2(KBUF, brow_s, 8 * (kk + 1) + bcsel, 13), bf[nxt]);
                }
                mma8(sacc[0], af[cur], bf[cur][0], bf[cur][1]);
                mma8(sacc[1], af[cur], bf[cur][2], bf[cur][3]);
            }
        }

        // Post-S rendezvous: K buffer free -> prefetch K(j+1) (lands during O).
        __syncthreads();
        if (tid == 0 && j < NT - 1) {
            MBAR_EXPECT_TX(kbar, 32768);
#pragma unroll
            for (int c = 0; c < 4; c++)
                TMA3D(KBUF + c * 8192, &kmap, 32 * c, (j + 1) * 64, b, kbar);
        }

        // ---- exp + mask; write P (tf32-rounded) into PBUF; row-sum ----
#pragma unroll
        for (int nb = 0; nb < 2; nb++) {
            float* c = sacc[nb];
            unsigned sh = 16 * quad + 8 * nb + 2 * tig;
            unsigned m0 = (unsigned)(mrow0 >> sh) & 3u;
            unsigned m1 = (unsigned)(mrow1 >> sh) & 3u;
            float p0 = (m0 & 1u) ? 0.f : rna_tf32(ex2f(c[0]));
            float p1 = (m0 & 2u) ? 0.f : rna_tf32(ex2f(c[1]));
            float p2 = (m1 & 1u) ? 0.f : rna_tf32(ex2f(c[2]));
            float p3 = (m1 & 2u) ? 0.f : rna_tf32(ex2f(c[3]));
            rsum[0] += p0 + p1;
            rsum[1] += p2 + p3;
            int cl = 16 * quad + 8 * nb + 2 * tig;
            sts2(swa2(PBUF, r0m,     cl, 13), p0, p1);
            sts2(swa2(PBUF, r0m + 8, cl, 13), p2, p3);
        }
        // P quarters visible across the mchunk's 4 quad-warps
        QUAD_BAR(1 + mchunk);

        MBAR_WAIT(vbar, ph);

        // ---- O-phase: O(16m x 32d per warp) += P(16m x 64k) @ V, pipelined ----
        {
            uint32_t af[2][4], bf[2][2][4];
            ldsm4(swa2(PBUF, arow0, acsel, 13), af[0]);
#pragma unroll
            for (int nbp = 0; nbp < 2; nbp++)
                ldsm4(swa2(VBUF, brow_o + 16 * nbp, bcsel, 14), bf[0][nbp]);
#pragma unroll
            for (int kk = 0; kk < 8; kk++) {
                const int cur = kk & 1, nxt = cur ^ 1;
                if (kk < 7) {
                    ldsm4(swa2(PBUF, arow0, 8 * (kk + 1) + acsel, 13), af[nxt]);
#pragma unroll
                    for (int nbp = 0; nbp < 2; nbp++)
                        ldsm4(swa2(VBUF, brow_o + 16 * nbp, 8 * (kk + 1) + bcsel, 14), bf[nxt][nbp]);
                }
#pragma unroll
                for (int nbp = 0; nbp < 2; nbp++) {
                    mma8(oacc[2 * nbp],     af[cur], bf[cur][nbp][0], bf[cur][nbp][1]);
                    mma8(oacc[2 * nbp + 1], af[cur], bf[cur][nbp][2], bf[cur][nbp][3]);
                }
            }
        }
    }

    // ---- Row sums: reduce over tig, combine quads via smem atomics ----
    rsum[0] += __shfl_xor_sync(0xffffffffu, rsum[0], 1);
    rsum[0] += __shfl_xor_sync(0xffffffffu, rsum[0], 2);
    rsum[1] += __shfl_xor_sync(0xffffffffu, rsum[1], 1);
    rsum[1] += __shfl_xor_sync(0xffffffffu, rsum[1], 2);
    if (tig == 0) {
        atomicAdd(&rs[r0m],     rsum[0]);
        atomicAdd(&rs[r0m + 8], rsum[1]);
    }
    __syncthreads();

    // ---- Normalize + store O (warp's 32 d-cols) ----
    const size_t obase = ((size_t)b * S_DIM + qt * 64) * D_DIM;
    {
        float inv0 = 1.0f / rs[r0m];
        float inv1 = 1.0f / rs[r0m + 8];
#pragma unroll
        for (int di = 0; di < 4; di++) {
            int col = 32 * quad + 8 * di + 2 * tig;
            float* c = oacc[di];
            float2* p0 = (float2*)(out + obase + (size_t)r0m * D_DIM + col);
            float2* p1 = (float2*)(out + obase + (size_t)(r0m + 8) * D_DIM + col);
            *p0 = make_float2(c[0] * inv0, c[1] * inv0);
            *p1 = make_float2(c[2] * inv1, c[3] * inv1);
        }
    }
}

// ---------------------------------------------------------------------------
// Host launcher
// ---------------------------------------------------------------------------
typedef CUresult (*EncodeFn)(CUtensorMap*, CUtensorMapDataType, cuuint32_t, void*,
                             const cuuint64_t*, const cuuint64_t*, const cuuint32_t*,
                             const cuuint32_t*, CUtensorMapInterleave, CUtensorMapSwizzle,
                             CUtensorMapL2promotion, CUtensorMapFloatOOBfill);

static void make_map(EncodeFn enc, CUtensorMap* m, void* ptr,
                     cuuint64_t d0, cuuint64_t d1, cuuint64_t d2, cuuint32_t box1) {
    cuuint64_t dims[3] = {d0, d1, d2};
    cuuint64_t strides[2] = {d0 * 4, d0 * d1 * 4};
    cuuint32_t box[3] = {32, box1, 1};
    cuuint32_t es[3] = {1, 1, 1};
    enc(m, CU_TENSOR_MAP_DATA_TYPE_FLOAT32, 3, ptr, dims, strides, box, es,
        CU_TENSOR_MAP_INTERLEAVE_NONE, CU_TENSOR_MAP_SWIZZLE_128B,
        CU_TENSOR_MAP_L2_PROMOTION_L2_128B, CU_TENSOR_MAP_FLOAT_OOB_FILL_NONE);
}

extern "C" void kernel_launch(void* const* d_in, const int* in_sizes, int n_in,
                              void* d_out, int out_size) {
    const float* q = (const float*)d_in[0];
    const float* k = (const float*)d_in[1];
    const float* v = (const float*)d_in[2];
    const void* mask = d_in[3];
    float* out = (float*)d_out;

    void *qr = 0, *kr = 0, *vt = 0, *mbp = 0;
    cudaGetSymbolAddress(&qr, g_Qr);
    cudaGetSymbolAddress(&kr, g_Kr);
    cudaGetSymbolAddress(&vt, g_VT);
    cudaGetSymbolAddress(&mbp, g_Mb);

    void* fptr = 0;
    cudaDriverEntryPointQueryResult qres;
    cudaGetDriverEntryPointByVersion("cuTensorMapEncodeTiled", &fptr, 12000,
                                     cudaEnableDefault, &qres);
    EncodeFn enc = (EncodeFn)fptr;
    if (!enc) return;

    CUtensorMap qmap, kmap, vmap;
    make_map(enc, &qmap, qr, D_DIM, S_DIM, B_DIM, 64);   // Q: box 32d x 64s
    make_map(enc, &kmap, kr, D_DIM, S_DIM, B_DIM, 64);   // K: box 32d x 64s
    make_map(enc, &vmap, vt, S_DIM, D_DIM, B_DIM, 128);  // V^T: box 32s x 128d

    // Prep passes (3 before attn_main so ncu's capture slot lands on attn_main)
    int nmb = (B_DIM * S_DIM * S_DIM) / 8;                // 8,388,608 output bytes
    prep_mask<<<nmb / 256, 256>>>((const uint4*)mask, (unsigned char*)mbp);
    int n4 = (B_DIM * S_DIM * D_DIM) / 4;                 // 1,048,576
    prep_qk<<<n4 / 256, 256>>>((const float4*)q, (const float4*)k, (float4*)qr, (float4*)kr);
    prep_vt<<<dim3(S_DIM / 32, D_DIM / 32, B_DIM), dim3(32, 32)>>>(v, (float*)vt);

    cudaFuncSetAttribute(attn_main, cudaFuncAttributeMaxDynamicSharedMemorySize, SMEM_BYTES);
    attn_main<<<B_DIM * 32, 512, SMEM_BYTES>>>(qmap, kmap, vmap,
                                               (const unsigned long long*)mbp, out);
}

// round 17
// speedup vs baseline: 1.2347x; 1.2347x over previous
#include <cuda_runtime.h>
#include <cuda.h>
#include <cstdint>
#include <cstddef>

// ---------------------------------------------------------------------------
// Problem constants
// ---------------------------------------------------------------------------
#define B_DIM 16
#define S_DIM 2048
#define D_DIM 128
#define NT 32             // 64-row k-tiles

// exp(x) = exp2(x*log2e); fold log2e/sqrt(128) into Q pre-scale
#define CQ_SCALE ((float)(1.4426950408889634 / 11.313708498984761))

// SMEM (per CTA, 113KB => 2 CTAs/SM):
// [0,256) rowsum f32[64]; [512..536) mbarriers;
// Q 32K @1024 | K 32K | V 32K | P 16K   (K,V single-buffered)
#define QBUF_OFF 1024
#define KBUF_OFF (QBUF_OFF + 32768)
#define VBUF_OFF (KBUF_OFF + 32768)
#define PBUF_OFF (VBUF_OFF + 32768)
#define SMEM_BYTES (PBUF_OFF + 16384)   // 115712 B = 113 KB

// ---------------------------------------------------------------------------
// Device scratch (static; no allocations allowed)
// ---------------------------------------------------------------------------
__device__ float g_Qr[B_DIM * S_DIM * D_DIM];                 // Q*(log2e/sqrt d), tf32-rounded
__device__ float g_Kr[B_DIM * S_DIM * D_DIM];                 // K tf32-rounded
__device__ float g_VT[B_DIM * D_DIM * S_DIM];                 // V^T [b][d][s], tf32-rounded
__device__ unsigned long long g_Mb[B_DIM * S_DIM * (S_DIM / 64)];  // mask bitpack

// ---------------------------------------------------------------------------
// PTX helpers
// ---------------------------------------------------------------------------
__device__ __forceinline__ uint32_t smem_u32(const void* p) {
    uint32_t a;
    asm("{ .reg .u64 t; cvta.to.shared.u64 t, %1; cvt.u32.u64 %0, t; }" : "=r"(a) : "l"(p));
    return a;
}
// cvt.rna.tf32.f32 requires a .b32 destination register.
__device__ __forceinline__ float rna_tf32(float x) {
    uint32_t r; asm("cvt.rna.tf32.f32 %0, %1;" : "=r"(r) : "f"(x));
    return __uint_as_float(r);
}
__device__ __forceinline__ float ex2f(float x) {
    float r; asm("ex2.approx.f32 %0, %1;" : "=f"(r) : "f"(x)); return r;
}

#define MBAR_INIT(a, c) \
    asm volatile("mbarrier.init.shared.b64 [%0], %1;" :: "r"(a), "r"((uint32_t)(c)) : "memory")
#define MBAR_EXPECT_TX(a, n) \
    asm volatile("mbarrier.arrive.expect_tx.shared.b64 _, [%0], %1;" :: "r"(a), "r"((uint32_t)(n)) : "memory")

#define MBAR_WAIT(a, ph) do {                                                     \
    uint32_t _m = (a), _p = (uint32_t)(ph), _d;                                   \
    asm volatile("{\n\t.reg .pred p;\n\t"                                         \
        "mbarrier.try_wait.parity.acquire.cta.shared::cta.b64 p, [%1], %2;\n\t"   \
        "selp.b32 %0, 1, 0, p;\n\t}"                                              \
        : "=r"(_d) : "r"(_m), "r"(_p) : "memory");                                \
    if (!_d) {                                                                    \
        asm volatile("{\n\t.reg .pred P1;\n\t"                                    \
            "WL_%=:\n\t"                                                          \
            "mbarrier.try_wait.parity.acquire.cta.shared::cta.b64 P1, [%0], %1, 0x989680;\n\t" \
            "@P1 bra.uni WD_%=;\n\t"                                              \
            "bra.uni WL_%=;\n\t"                                                  \
            "WD_%=:\n\t}"                                                         \
            :: "r"(_m), "r"(_p) : "memory");                                      \
    }                                                                             \
} while (0)

// Pairwise named barrier: 64 threads (warps mchunk and mchunk+4)
#define PAIR_BAR(id) \
    asm volatile("bar.sync %0, 64;" :: "r"((uint32_t)(id)) : "memory")

#define TMA3D(dst, map, x, y, z, mb)                                              \
    asm volatile("cp.async.bulk.tensor.3d.shared::cta.global.tile.mbarrier::complete_tx::bytes " \
                 "[%0], [%1, {%2, %3, %4}], [%5];"                                \
                 :: "r"(dst), "l"(map), "r"((int)(x)), "r"((int)(y)), "r"((int)(z)), "r"(mb) : "memory")

// Swizzled address of f32 element (row, col): region = 32 f32-cols wide,
// rows*128B tall; rshift = log2(region bytes). TMA SW128 swizzle inside.
__device__ __forceinline__ uint32_t swa2(uint32_t buf, int row, int col, int rshift) {
    uint32_t byte = (uint32_t)(row * 128 + (col & 31) * 4);
    return buf + (((uint32_t)col >> 5) << rshift) + (byte ^ ((byte >> 3) & 0x70));
}

__device__ __forceinline__ void ldsm4(uint32_t addr, uint32_t* r) {
    asm volatile("ldmatrix.sync.aligned.m8n8.x4.shared.b16 {%0,%1,%2,%3}, [%4];"
                 : "=r"(r[0]), "=r"(r[1]), "=r"(r[2]), "=r"(r[3]) : "r"(addr));
}

// Non-volatile: pure register op; lets the compiler schedule MMAs freely.
__device__ __forceinline__ void mma8(float* c, const uint32_t* a, uint32_t b0, uint32_t b1) {
    asm("mma.sync.aligned.m16n8k8.row.col.f32.tf32.tf32.f32 "
        "{%0,%1,%2,%3}, {%4,%5,%6,%7}, {%8,%9}, {%0,%1,%2,%3};"
        : "+f"(c[0]), "+f"(c[1]), "+f"(c[2]), "+f"(c[3])
        : "r"(a[0]), "r"(a[1]), "r"(a[2]), "r"(a[3]), "r"(b0), "r"(b1));
}

__device__ __forceinline__ void sts2(uint32_t addr, float x, float y) {
    asm volatile("st.shared.v2.f32 [%0], {%1,%2};" :: "r"(addr), "f"(x), "f"(y) : "memory");
}

// ---------------------------------------------------------------------------
// Prep kernels
// ---------------------------------------------------------------------------
__global__ void prep_qk(const float4* __restrict__ q, const float4* __restrict__ k,
                        float4* __restrict__ qo, float4* __restrict__ ko) {
    int i = blockIdx.x * blockDim.x + threadIdx.x;
    float4 a = q[i];
    a.x = rna_tf32(a.x * CQ_SCALE); a.y = rna_tf32(a.y * CQ_SCALE);
    a.z = rna_tf32(a.z * CQ_SCALE); a.w = rna_tf32(a.w * CQ_SCALE);
    qo[i] = a;
    float4 b = k[i];
    b.x = rna_tf32(b.x); b.y = rna_tf32(b.y);
    b.z = rna_tf32(b.z); b.w = rna_tf32(b.w);
    ko[i] = b;
}

// V [b][s][d] -> VT [b][d][s], tf32-rounded.
// 32x32 tile, 256 threads (32x8), 4 elements/thread for ILP; coalesced
// on both the read (d-contiguous) and write (s-contiguous) sides.
__global__ void prep_vt(const float* __restrict__ v, float* __restrict__ vt) {
    __shared__ float t[32][33];
    int b = blockIdx.z;
    int s0 = blockIdx.x * 32, d0 = blockIdx.y * 32;
    const float* vb = v + (size_t)b * S_DIM * D_DIM;
    float* vtb = vt + (size_t)b * D_DIM * S_DIM;
    int tx = threadIdx.x, ty = threadIdx.y;
#pragma unroll
    for (int yy = 0; yy < 4; yy++) {
        int row = ty + 8 * yy;
        t[row][tx] = rna_tf32(vb[(size_t)(s0 + row) * D_DIM + d0 + tx]);
    }
    __syncthreads();
#pragma unroll
    for (int yy = 0; yy < 4; yy++) {
        int row = ty + 8 * yy;
        vtb[(size_t)(d0 + row) * S_DIM + s0 + tx] = t[tx][row];
    }
}

// Mask arrives as 4-byte elements (verified in R7 profile: 264MB DRAM read).
// out byte i <- mask elements [8i, 8i+8); bit j of byte i = element 8i+j.
__global__ void prep_mask(const uint4* __restrict__ m, unsigned char* __restrict__ o) {
    int i = blockIdx.x * blockDim.x + threadIdx.x;
    const uint4* p = m + (size_t)i * 2;
    uint4 a = p[0], b = p[1];
    unsigned v =
        (a.x != 0u ? 1u : 0u) | (a.y != 0u ? 2u : 0u) |
        (a.z != 0u ? 4u : 0u) | (a.w != 0u ? 8u : 0u) |
        (b.x != 0u ? 16u : 0u) | (b.y != 0u ? 32u : 0u) |
        (b.z != 0u ? 64u : 0u) | (b.w != 0u ? 128u : 0u);
    o[i] = (unsigned char)v;
}

// ---------------------------------------------------------------------------
// Main fused attention kernel — R15 (best): 64 q-rows/CTA, 2 CTAs/SM,
// 64-row k-tiles, single-buffered K/V, software-pipelined inner loops.
// ---------------------------------------------------------------------------
__global__ void __launch_bounds__(256, 2) attn_main(
    const __grid_constant__ CUtensorMap qmap,   // box {32,64}
    const __grid_constant__ CUtensorMap kmap,   // box {32,64}
    const __grid_constant__ CUtensorMap vmap,   // box {32,128}
    const unsigned long long* __restrict__ mbits,
    float* __restrict__ out)
{
    extern __shared__ char smem[];
    float* rs = (float*)smem;               // rowsum[64]
    const uint32_t sb = smem_u32(smem);
    const uint32_t kbar = sb + 512, vbar = sb + 520;
    const uint32_t QBUF = sb + QBUF_OFF, KBUF = sb + KBUF_OFF;
    const uint32_t VBUF = sb + VBUF_OFF, PBUF = sb + PBUF_OFF;

    const int tid = threadIdx.x, wid = tid >> 5, lane = tid & 31;
    const int mchunk = wid & 3, half = wid >> 2;
    const int tig = lane & 3, g = lane >> 2;
    const int b = blockIdx.x >> 5, qt = blockIdx.x & 31;

    // ldmatrix lane-role rows
    const int arow0  = 16 * mchunk + (lane & 7) + ((lane >> 3) & 1) * 8;  // A rows (m16)
    const int brow_s = 32 * half + (lane & 7) + ((lane >> 4) & 1) * 8;    // S-phase B (+16*nbp, nbp<2)
    const int brow_o = 64 * half + (lane & 7) + ((lane >> 4) & 1) * 8;    // O-phase B (+16*nbp, nbp<4)
    const int acsel = ((lane >> 4) & 1) * 4;
    const int bcsel = ((lane >> 3) & 1) * 4;

    if (tid < 64) rs[tid] = 0.0f;
    if (tid == 0) { MBAR_INIT(kbar, 1); MBAR_INIT(vbar, 1); }
    __syncthreads();

    // Prologue: Q (32K) + K(0) (32K) on kbar; V(0) (32K) on vbar
    if (tid == 0) {
        MBAR_EXPECT_TX(kbar, 65536);
#pragma unroll
        for (int c = 0; c < 4; c++) {
            TMA3D(QBUF + c * 8192, &qmap, 32 * c, qt * 64, b, kbar);
            TMA3D(KBUF + c * 8192, &kmap, 32 * c, 0, b, kbar);
        }
        MBAR_EXPECT_TX(vbar, 32768);
#pragma unroll
        for (int c = 0; c < 2; c++)
            TMA3D(VBUF + c * 16384, &vmap, 32 * c, 0, b, vbar);
    }

    float oacc[8][4];
#pragma unroll
    for (int nb = 0; nb < 8; nb++)
#pragma unroll
        for (int i = 0; i < 4; i++) oacc[nb][i] = 0.0f;

    float rsum[2] = {0.f, 0.f};
    const size_t mrow_base = ((size_t)b * S_DIM + qt * 64) * (S_DIM / 64);
    const int r0m = 16 * mchunk + g;

    for (int j = 0; j < NT; j++) {
        const int ph = j & 1;

        // Top-of-tile rendezvous (j>0): all warps done O(j-1) -> V buffer free.
        if (j > 0) {
            __syncthreads();
            if (tid == 0) {
                MBAR_EXPECT_TX(vbar, 32768);
#pragma unroll
                for (int c = 0; c < 2; c++)
                    TMA3D(VBUF + c * 16384, &vmap, j * 64 + 32 * c, 0, b, vbar);
            }
        }

        // Mask u64s (issued before barrier wait to hide latency)
        unsigned long long mrow0 = __ldg(mbits + mrow_base + (size_t)r0m * 32 + j);
        unsigned long long mrow1 = __ldg(mbits + mrow_base + (size_t)(r0m + 8) * 32 + j);

        MBAR_WAIT(kbar, ph);

        // ---- S-phase: S(64x64) = Q @ K(j)^T over d (16 k8-steps) ----
        // Software-pipelined: fragments for kk+1 load before kk's MMAs.
        float sacc[4][4];
#pragma unroll
        for (int nb = 0; nb < 4; nb++)
#pragma unroll
            for (int i = 0; i < 4; i++) sacc[nb][i] = 0.0f;

        {
            uint32_t af[2][4], bf[2][2][4];
            ldsm4(swa2(QBUF, arow0, acsel, 13), af[0]);
            ldsm4(swa2(KBUF, brow_s,      bcsel, 13), bf[0][0]);
            ldsm4(swa2(KBUF, brow_s + 16, bcsel, 13), bf[0][1]);
#pragma unroll
            for (int kk = 0; kk < 16; kk++) {
                const int cur = kk & 1, nxt = cur ^ 1;
                if (kk < 15) {
                    ldsm4(swa2(QBUF, arow0, 8 * (kk + 1) + acsel, 13), af[nxt]);
                    ldsm4(swa2(KBUF, brow_s,      8 * (kk + 1) + bcsel, 13), bf[nxt][0]);
                    ldsm4(swa2(KBUF, brow_s + 16, 8 * (kk + 1) + bcsel, 13), bf[nxt][1]);
                }
                mma8(sacc[0], af[cur], bf[cur][0][0], bf[cur][0][1]);
                mma8(sacc[1], af[cur], bf[cur][0][2], bf[cur][0][3]);
                mma8(sacc[2], af[cur], bf[cur][1][0], bf[cur][1][1]);
                mma8(sacc[3], af[cur], bf[cur][1][2], bf[cur][1][3]);
            }
        }

        // Post-S rendezvous: K buffer free -> prefetch K(j+1) (lands during O).
        __syncthreads();
        if (tid == 0 && j < NT - 1) {
            MBAR_EXPECT_TX(kbar, 32768);
#pragma unroll
            for (int c = 0; c < 4; c++)
                TMA3D(KBUF + c * 8192, &kmap, 32 * c, (j + 1) * 64, b, kbar);
        }

        // ---- exp + mask; write P (tf32-rounded) into PBUF; row-sum ----
#pragma unroll
        for (int nb = 0; nb < 4; nb++) {
            float* c = sacc[nb];
            unsigned sh = 32 * half + 8 * nb + 2 * tig;
            unsigned m0 = (unsigned)(mrow0 >> sh) & 3u;
            unsigned m1 = (unsigned)(mrow1 >> sh) & 3u;
            float p0 = (m0 & 1u) ? 0.f : rna_tf32(ex2f(c[0]));
            float p1 = (m0 & 2u) ? 0.f : rna_tf32(ex2f(c[1]));
            float p2 = (m1 & 1u) ? 0.f : rna_tf32(ex2f(c[2]));
            float p3 = (m1 & 2u) ? 0.f : rna_tf32(ex2f(c[3]));
            rsum[0] += p0 + p1;
            rsum[1] += p2 + p3;
            int cl = 32 * half + 8 * nb + 2 * tig;
            sts2(swa2(PBUF, r0m,     cl, 13), p0, p1);
            sts2(swa2(PBUF, r0m + 8, cl, 13), p2, p3);
        }
        // P-halves exchange within the m-chunk pair only (warps mchunk, mchunk+4)
        PAIR_BAR(1 + mchunk);

        MBAR_WAIT(vbar, ph);

        // ---- O-phase: O(64x128) += P(64x64) @ V(j)(64x128), pipelined ----
        {
            uint32_t af[2][4], bf[2][4][4];
            ldsm4(swa2(PBUF, arow0, acsel, 13), af[0]);
#pragma unroll
            for (int nbp = 0; nbp < 4; nbp++)
                ldsm4(swa2(VBUF, brow_o + 16 * nbp, bcsel, 14), bf[0][nbp]);
#pragma unroll
            for (int kk = 0; kk < 8; kk++) {
                const int cur = kk & 1, nxt = cur ^ 1;
                if (kk < 7) {
                    ldsm4(swa2(PBUF, arow0, 8 * (kk + 1) + acsel, 13), af[nxt]);
#pragma unroll
                    for (int nbp = 0; nbp < 4; nbp++)
                        ldsm4(swa2(VBUF, brow_o + 16 * nbp, 8 * (kk + 1) + bcsel, 14), bf[nxt][nbp]);
                }
#pragma unroll
                for (int nbp = 0; nbp < 4; nbp++) {
                    mma8(oacc[2 * nbp],     af[cur], bf[cur][nbp][0], bf[cur][nbp][1]);
                    mma8(oacc[2 * nbp + 1], af[cur], bf[cur][nbp][2], bf[cur][nbp][3]);
                }
            }
        }
    }

    // ---- Row sums: reduce over tig, combine halves via smem atomics ----
    rsum[0] += __shfl_xor_sync(0xffffffffu, rsum[0], 1);
    rsum[0] += __shfl_xor_sync(0xffffffffu, rsum[0], 2);
    rsum[1] += __shfl_xor_sync(0xffffffffu, rsum[1], 1);
    rsum[1] += __shfl_xor_sync(0xffffffffu, rsum[1], 2);
    if (tig == 0) {
        atomicAdd(&rs[r0m],     rsum[0]);
        atomicAdd(&rs[r0m + 8], rsum[1]);
    }
    __syncthreads();

    // ---- Normalize + store O ----
    const size_t obase = ((size_t)b * S_DIM + qt * 64) * D_DIM;
    {
        float inv0 = 1.0f / rs[r0m];
        float inv1 = 1.0f / rs[r0m + 8];
#pragma unroll
        for (int di = 0; di < 8; di++) {
            int col = 64 * half + 8 * di + 2 * tig;
            float* c = oacc[di];
            float2* p0 = (float2*)(out + obase + (size_t)r0m * D_DIM + col);
            float2* p1 = (float2*)(out + obase + (size_t)(r0m + 8) * D_DIM + col);
            *p0 = make_float2(c[0] * inv0, c[1] * inv0);
            *p1 = make_float2(c[2] * inv1, c[3] * inv1);
        }
    }
}

// ---------------------------------------------------------------------------
// Host launcher
// ---------------------------------------------------------------------------
typedef CUresult (*EncodeFn)(CUtensorMap*, CUtensorMapDataType, cuuint32_t, void*,
                             const cuuint64_t*, const cuuint64_t*, const cuuint32_t*,
                             const cuuint32_t*, CUtensorMapInterleave, CUtensorMapSwizzle,
                             CUtensorMapL2promotion, CUtensorMapFloatOOBfill);

static void make_map(EncodeFn enc, CUtensorMap* m, void* ptr,
                     cuuint64_t d0, cuuint64_t d1, cuuint64_t d2, cuuint32_t box1) {
    cuuint64_t dims[3] = {d0, d1, d2};
    cuuint64_t strides[2] = {d0 * 4, d0 * d1 * 4};
    cuuint32_t box[3] = {32, box1, 1};
    cuuint32_t es[3] = {1, 1, 1};
    enc(m, CU_TENSOR_MAP_DATA_TYPE_FLOAT32, 3, ptr, dims, strides, box, es,
        CU_TENSOR_MAP_INTERLEAVE_NONE, CU_TENSOR_MAP_SWIZZLE_128B,
        CU_TENSOR_MAP_L2_PROMOTION_L2_128B, CU_TENSOR_MAP_FLOAT_OOB_FILL_NONE);
}

extern "C" void kernel_launch(void* const* d_in, const int* in_sizes, int n_in,
                              void* d_out, int out_size) {
    const float* q = (const float*)d_in[0];
    const float* k = (const float*)d_in[1];
    const float* v = (const float*)d_in[2];
    const void* mask = d_in[3];
    float* out = (float*)d_out;

    void *qr = 0, *kr = 0, *vt = 0, *mbp = 0;
    cudaGetSymbolAddress(&qr, g_Qr);
    cudaGetSymbolAddress(&kr, g_Kr);
    cudaGetSymbolAddress(&vt, g_VT);
    cudaGetSymbolAddress(&mbp, g_Mb);

    void* fptr = 0;
    cudaDriverEntryPointQueryResult qres;
    cudaGetDriverEntryPointByVersion("cuTensorMapEncodeTiled", &fptr, 12000,
                                     cudaEnableDefault, &qres);
    EncodeFn enc = (EncodeFn)fptr;
    if (!enc) return;

    CUtensorMap qmap, kmap, vmap;
    make_map(enc, &qmap, qr, D_DIM, S_DIM, B_DIM, 64);   // Q: box 32d x 64s
    make_map(enc, &kmap, kr, D_DIM, S_DIM, B_DIM, 64);   // K: box 32d x 64s
    make_map(enc, &vmap, vt, S_DIM, D_DIM, B_DIM, 128);  // V^T: box 32s x 128d

    // Prep passes (3 before attn_main so ncu's capture slot lands on attn_main)
    int nmb = (B_DIM * S_DIM * S_DIM) / 8;                // 8,388,608 output bytes
    prep_mask<<<nmb / 256, 256>>>((const uint4*)mask, (unsigned char*)mbp);
    int n4 = (B_DIM * S_DIM * D_DIM) / 4;                 // 1,048,576
    prep_qk<<<n4 / 256, 256>>>((const float4*)q, (const float4*)k, (float4*)qr, (float4*)kr);
    prep_vt<<<dim3(S_DIM / 32, D_DIM / 32, B_DIM), dim3(32, 8)>>>(v, (float*)vt);

    cudaFuncSetAttribute(attn_main, cudaFuncAttributeMaxDynamicSharedMemorySize, SMEM_BYTES);
    attn_main<<<B_DIM * 32, 256, SMEM_BYTES>>>(qmap, kmap, vmap,
                                               (const unsigned long long*)mbp, out);
}